// round 14
// baseline (speedup 1.0000x reference)
#include <cuda_runtime.h>
#include <cuda_bf16.h>
#include <cstdint>

// Shapes: B=8, C=256, N=1024, V=12. NVC = N*V = 12288.
// Identity: attention output == v (softmax over j sums to 1; j only indexes attn),
// so the net is 4 masked-batchstat-BN 1x1 convs (GEMMs) + residuals.
// Round 14: r13 persistent pipeline + MMA DEPENDENCY FIX: the 3 split-term MMAs
// per (mt,nt) were issued back-to-back on the same accumulator (chain latency
// ~3x24cyc); reordered into 3 passes over nt so consecutive MMAs hit different
// accumulators.

#define NVC 12288
#define NB 8
#define CNT_INV (1.0f/98304.0f)
#define EPS 1e-5f
#define PGRID 296

__device__ float g_emb[NB * 64 * NVC];
__device__ float g_bufa[NB * 256 * NVC];
__device__ float g_bufb[NB * 256 * NVC];
__device__ float g_stats[2048];
__device__ __nv_bfloat16 g_whi[163840];
__device__ __nv_bfloat16 g_wlo[163840];

#define WOFF_E  0
#define WOFF_A  16384
#define WOFF_O  32768
#define WOFF_F  98304

__global__ void zero_stats() {
    int i = blockIdx.x * blockDim.x + threadIdx.x;
    if (i < 2048) g_stats[i] = 0.0f;
}

__global__ void split_weights(const float* __restrict__ We, const float* __restrict__ Wa,
                              const float* __restrict__ Wo, const float* __restrict__ Wf)
{
    int i = blockIdx.x * blockDim.x + threadIdx.x;
    if (i >= 163840) return;
    float w;
    if (i < 16384)       w = We[i];
    else if (i < 32768)  w = Wa[512 * 64 + (i - 16384)];
    else if (i < 98304)  w = Wo[i - 32768];
    else                 w = Wf[i - 98304];
    __nv_bfloat16 h = __float2bfloat16(w);
    g_whi[i] = h;
    g_wlo[i] = __float2bfloat16(w - __bfloat162float(h));
}

__device__ __forceinline__ uint32_t smem_u32(const void* p) {
    uint32_t a;
    asm("{ .reg .u64 t; cvta.to.shared.u64 t, %1; cvt.u32.u64 %0, t; }" : "=r"(a) : "l"(p));
    return a;
}
__device__ __forceinline__ void cp_async16(uint32_t dst, const void* src) {
    asm volatile("cp.async.cg.shared.global [%0], [%1], 16;" :: "r"(dst), "l"(src));
}
#define CP_COMMIT() asm volatile("cp.async.commit_group;" ::: "memory")
#define CP_WAIT0()  asm volatile("cp.async.wait_group 0;" ::: "memory")

#define LDSM_X4(r0, r1, r2, r3, addr) \
    asm volatile("ldmatrix.sync.aligned.m8n8.x4.shared.b16 {%0,%1,%2,%3}, [%4];" \
        : "=r"(r0), "=r"(r1), "=r"(r2), "=r"(r3) : "r"(addr))
#define LDSM_X4T(r0, r1, r2, r3, addr) \
    asm volatile("ldmatrix.sync.aligned.m8n8.x4.trans.shared.b16 {%0,%1,%2,%3}, [%4];" \
        : "=r"(r0), "=r"(r1), "=r"(r2), "=r"(r3) : "r"(addr))

__device__ __forceinline__ void mma16816(float* d, const uint32_t* a, const uint32_t* b) {
    asm volatile("mma.sync.aligned.m16n8k16.row.col.f32.bf16.bf16.f32 "
        "{%0,%1,%2,%3}, {%4,%5,%6,%7}, {%8,%9}, {%0,%1,%2,%3};"
        : "+f"(d[0]), "+f"(d[1]), "+f"(d[2]), "+f"(d[3])
        : "r"(a[0]), "r"(a[1]), "r"(a[2]), "r"(a[3]), "r"(b[0]), "r"(b[1]));
}

__device__ __forceinline__ uint32_t cvt2(float h, float l) {
    uint32_t r;
    asm("cvt.rn.bf16x2.f32 %0, %1, %2;" : "=r"(r) : "f"(h), "f"(l));
    return r;
}
__device__ __forceinline__ void split4f(float4 v, uint2& hi, uint2& lo) {
    uint32_t h01 = cvt2(v.y, v.x);
    uint32_t h23 = cvt2(v.w, v.z);
    float f0 = __uint_as_float(h01 << 16);
    float f1 = __uint_as_float(h01 & 0xFFFF0000u);
    float f2 = __uint_as_float(h23 << 16);
    float f3 = __uint_as_float(h23 & 0xFFFF0000u);
    uint32_t l01 = cvt2(v.y - f1, v.x - f0);
    uint32_t l23 = cvt2(v.w - f3, v.z - f2);
    hi.x = h01; hi.y = h23;
    lo.x = l01; lo.y = l23;
}

// smem layout helper (bytes)
template<int BM, int K>
struct SmemCfg {
    static constexpr int BN = 128, BK = 32, SA = 40, SB = 136;
    static constexpr int XRAW = 2 * BK * BN * 4;
    static constexpr int APL  = 2 * BM * SA * 2;
    static constexpr int BPL  = BK * SB * 2;
    static constexpr int O_AH = XRAW;
    static constexpr int O_AL = O_AH + APL;
    static constexpr int O_BH = O_AL + APL;
    static constexpr int O_BL = O_BH + BPL;
    static constexpr int O_MK = O_BL + BPL;
    static constexpr int O_AS = O_MK + BN * 4;
    static constexpr int O_CS = O_AS + K * 4;
    static constexpr int O_RS = O_CS + K * 4;
    static constexpr int O_RQ = O_RS + BM * 4;
    static constexpr int TOTAL = O_RQ + BM * 4;
};

// Persistent layer kernel: grid = PGRID CTAs loop over all tiles.
template<int M, int K, int BM, int MODE>
__global__ void __launch_bounds__(256, 2)
mma_layer(const float* __restrict__ X,
          const __nv_bfloat16* __restrict__ Whi, const __nv_bfloat16* __restrict__ Wlo,
          const float* __restrict__ bias, const float* __restrict__ mask,
          const float* __restrict__ pssum, const float* __restrict__ pssq,
          const float* __restrict__ pg, const float* __restrict__ pb,
          const float* __restrict__ resid,
          float* __restrict__ Y, float* __restrict__ ssum, float* __restrict__ ssq)
{
    using CFG = SmemCfg<BM, K>;
    constexpr int BN = 128, BK = 32, SA = 40, SB = 136;
    constexpr int WM = BM / 2;
    constexpr int MTI = WM / 16;
    constexpr int NCH = K / BK;
    constexpr int ACP = BM * BK / 8 / 256;
    constexpr int TX = NVC / BN;
    constexpr int TY = M / BM;
    constexpr int NT = TX * TY * NB;

    extern __shared__ char sm[];
    float* Xraw = reinterpret_cast<float*>(sm);
    __nv_bfloat16* Ah = reinterpret_cast<__nv_bfloat16*>(sm + CFG::O_AH);
    __nv_bfloat16* Al = reinterpret_cast<__nv_bfloat16*>(sm + CFG::O_AL);
    __nv_bfloat16* Bh = reinterpret_cast<__nv_bfloat16*>(sm + CFG::O_BH);
    __nv_bfloat16* Bl = reinterpret_cast<__nv_bfloat16*>(sm + CFG::O_BL);
    float* maskS = reinterpret_cast<float*>(sm + CFG::O_MK);
    float* aS    = reinterpret_cast<float*>(sm + CFG::O_AS);
    float* cS    = reinterpret_cast<float*>(sm + CFG::O_CS);
    float* rs    = reinterpret_cast<float*>(sm + CFG::O_RS);
    float* rq    = reinterpret_cast<float*>(sm + CFG::O_RQ);

    const int tid = threadIdx.x, wid = tid >> 5, lid = tid & 31;
    const int warp_m = wid >> 2, warp_n = wid & 3;
    const int g = lid >> 2, t4 = lid & 3;
    const int lq = lid >> 3, lr = lid & 7;

    const uint32_t xrS = smem_u32(Xraw);
    const uint32_t ahS = smem_u32(Ah);
    const uint32_t alS = smem_u32(Al);

    if (MODE != 0) {
        for (int k = tid; k < K; k += 256) {
            float mu  = pssum[k] * CNT_INV;
            float var = fmaf(-mu, mu, pssq[k] * CNT_INV);
            float a   = pg[k] * rsqrtf(var + EPS);
            aS[k] = a;
            cS[k] = fmaf(-mu, a, pb[k]);
        }
    }

#pragma unroll 1
    for (int tile = blockIdx.x; tile < NT; tile += PGRID) {
        const int b   = tile / (TX * TY);
        const int rem = tile % (TX * TY);
        const int row0 = (rem / TX) * BM;
        const int col0 = (rem % TX) * BN;

        const float* Xb = X + (size_t)b * K * NVC + col0;
        const float* Rb = (MODE == 2) ? resid + (size_t)b * K * NVC + col0 : nullptr;
        const float* Mb = mask + (size_t)b * NVC + col0;
        float*       Yb = Y + (size_t)b * M * NVC + col0;

        for (int i = tid; i < BN / 4; i += 256)
            reinterpret_cast<float4*>(maskS)[i] = reinterpret_cast<const float4*>(Mb)[i];
        for (int i = tid; i < BM; i += 256) { rs[i] = 0.0f; rq[i] = 0.0f; }

        float acc[MTI][4][4];
#pragma unroll
        for (int mt = 0; mt < MTI; mt++)
#pragma unroll
            for (int nt = 0; nt < 4; nt++)
#pragma unroll
                for (int r = 0; r < 4; r++) acc[mt][nt][r] = 0.0f;

        auto issue_chunk = [&](int ch) {
            const int buf = ch & 1;
            const int k0 = ch * BK;
#pragma unroll
            for (int it = 0; it < 4; it++) {
                const int idx = tid + it * 256;
                const int kk = idx >> 5;
                const int c16 = (idx & 31) * 4;
                cp_async16(xrS + (uint32_t)(buf * BK * BN + kk * BN + c16) * 4,
                           Xb + (size_t)(k0 + kk) * NVC + c16);
            }
#pragma unroll
            for (int it = 0; it < ACP; it++) {
                const int idx = tid + it * 256;
                const int m  = idx >> 2;
                const int kq = idx & 3;
                const size_t goff = (size_t)(row0 + m) * K + k0 + kq * 8;
                const uint32_t soff = (uint32_t)(buf * BM * SA + m * SA + kq * 8) * 2;
                cp_async16(ahS + soff, Whi + goff);
                cp_async16(alS + soff, Wlo + goff);
            }
            CP_COMMIT();
        };

        issue_chunk(0);
        CP_WAIT0();
        __syncthreads();

#pragma unroll 1
        for (int ch = 0; ch < NCH; ch++) {
            const int buf = ch & 1;
            const int k0 = ch * BK;

            float4 rr[4];
            if (MODE == 2) {
#pragma unroll
                for (int it = 0; it < 4; it++) {
                    const int idx = tid + it * 256;
                    const int kk = idx >> 5;
                    const int c16 = (idx & 31) * 4;
                    rr[it] = *reinterpret_cast<const float4*>(Rb + (size_t)(k0 + kk) * NVC + c16);
                }
            }
#pragma unroll
            for (int it = 0; it < 4; it++) {
                const int idx = tid + it * 256;
                const int kk = idx >> 5;
                const int c16 = (idx & 31) * 4;
                float4 v = *reinterpret_cast<const float4*>(&Xraw[buf * BK * BN + kk * BN + c16]);
                if (MODE != 0) {
                    const float a = aS[k0 + kk], cc = cS[k0 + kk];
                    float4 mk = *reinterpret_cast<const float4*>(&maskS[c16]);
                    v.x = mk.x > 0.0f ? fmaxf(fmaf(v.x, a, cc), 0.0f) : 0.0f;
                    v.y = mk.y > 0.0f ? fmaxf(fmaf(v.y, a, cc), 0.0f) : 0.0f;
                    v.z = mk.z > 0.0f ? fmaxf(fmaf(v.z, a, cc), 0.0f) : 0.0f;
                    v.w = mk.w > 0.0f ? fmaxf(fmaf(v.w, a, cc), 0.0f) : 0.0f;
                    if (MODE == 2) {
                        v.x += rr[it].x; v.y += rr[it].y; v.z += rr[it].z; v.w += rr[it].w;
                    }
                }
                uint2 hi, lo;
                split4f(v, hi, lo);
                *reinterpret_cast<uint2*>(&Bh[kk * SB + c16]) = hi;
                *reinterpret_cast<uint2*>(&Bl[kk * SB + c16]) = lo;
            }
            __syncthreads();

            if (ch + 1 < NCH) issue_chunk(ch + 1);

#pragma unroll
            for (int ks = 0; ks < 2; ks++) {
                const int kb = ks * 16;
                uint32_t bh[4][2], bl[4][2];
#pragma unroll
                for (int p = 0; p < 2; p++) {
                    const int nb = warp_n * 32 + p * 16;
                    const int brow = kb + (lq & 1) * 8 + lr;
                    const int bcol = nb + (lq >> 1) * 8;
                    uint32_t r0, r1, r2, r3;
                    LDSM_X4T(r0, r1, r2, r3, smem_u32(&Bh[brow * SB + bcol]));
                    bh[2 * p][0] = r0; bh[2 * p][1] = r1;
                    bh[2 * p + 1][0] = r2; bh[2 * p + 1][1] = r3;
                    LDSM_X4T(r0, r1, r2, r3, smem_u32(&Bl[brow * SB + bcol]));
                    bl[2 * p][0] = r0; bl[2 * p][1] = r1;
                    bl[2 * p + 1][0] = r2; bl[2 * p + 1][1] = r3;
                }
#pragma unroll
                for (int mt = 0; mt < MTI; mt++) {
                    const int m0 = warp_m * WM + mt * 16;
                    const int arow = m0 + (lq & 1) * 8 + lr;
                    const int acol = kb + (lq >> 1) * 8;
                    uint32_t ah[4], al[4];
                    LDSM_X4(ah[0], ah[1], ah[2], ah[3],
                            smem_u32(&Ah[buf * BM * SA + arow * SA + acol]));
                    LDSM_X4(al[0], al[1], al[2], al[3],
                            smem_u32(&Al[buf * BM * SA + arow * SA + acol]));
                    // 3 passes: consecutive MMAs hit DIFFERENT accumulators
                    // (was: 3 back-to-back dependent MMAs on the same acc)
#pragma unroll
                    for (int nt = 0; nt < 4; nt++)
                        mma16816(acc[mt][nt], ah, bh[nt]);
#pragma unroll
                    for (int nt = 0; nt < 4; nt++)
                        mma16816(acc[mt][nt], ah, bl[nt]);
#pragma unroll
                    for (int nt = 0; nt < 4; nt++)
                        mma16816(acc[mt][nt], al, bh[nt]);
                }
            }
            if (ch + 1 < NCH) CP_WAIT0();
            __syncthreads();
        }

        // ---- epilogue: bias + mask, store raw Y (row0 + rowl), per-row stats ----
#pragma unroll
        for (int mt = 0; mt < MTI; mt++) {
#pragma unroll
            for (int h = 0; h < 2; h++) {
                const int rowl = warp_m * WM + mt * 16 + h * 8 + g;
                const float bv = __ldg(&bias[row0 + rowl]);
                float s = 0.0f, q = 0.0f;
                float* yrow = Yb + (size_t)(row0 + rowl) * NVC;
#pragma unroll
                for (int nt = 0; nt < 4; nt++) {
                    const int coll = warp_n * 32 + nt * 8 + t4 * 2;
                    float y0 = (acc[mt][nt][h * 2 + 0] + bv) * maskS[coll];
                    float y1 = (acc[mt][nt][h * 2 + 1] + bv) * maskS[coll + 1];
                    s += y0 + y1;
                    q += y0 * y0 + y1 * y1;
                    float2 o; o.x = y0; o.y = y1;
                    *reinterpret_cast<float2*>(yrow + coll) = o;
                }
                s += __shfl_xor_sync(0xFFFFFFFF, s, 1);
                s += __shfl_xor_sync(0xFFFFFFFF, s, 2);
                q += __shfl_xor_sync(0xFFFFFFFF, q, 1);
                q += __shfl_xor_sync(0xFFFFFFFF, q, 2);
                if (t4 == 0) {
                    atomicAdd(&rs[rowl], s);
                    atomicAdd(&rq[rowl], q);
                }
            }
        }
        __syncthreads();
        for (int i = tid; i < BM; i += 256) {
            atomicAdd(&ssum[row0 + i], rs[i]);
            atomicAdd(&ssq[row0 + i], rq[i]);
        }
        __syncthreads();
    }
}

// out = feats + bnmask_o(rawO) + bnmask_f(rawF)
__global__ void __launch_bounds__(256)
final_fuse(const float* __restrict__ rawO, const float* __restrict__ rawF,
           const float* __restrict__ feats, const float* __restrict__ mask,
           const float* __restrict__ st,
           const float* __restrict__ go, const float* __restrict__ bno,
           const float* __restrict__ gf, const float* __restrict__ bnf,
           float* __restrict__ out)
{
    size_t i = (size_t)blockIdx.x * blockDim.x + threadIdx.x;
    constexpr size_t TOT4 = (size_t)NB * 256 * NVC / 4;
    if (i >= TOT4) return;
    size_t e = i * 4;
    int col = (int)(e % NVC);
    size_t bm = e / NVC;
    int m = (int)(bm % 256);
    int b = (int)(bm / 256);

    float muo  = st[640 + m] * CNT_INV;
    float varo = fmaf(-muo, muo, st[896 + m] * CNT_INV);
    float ao   = go[m] * rsqrtf(varo + EPS);
    float co   = fmaf(-muo, ao, bno[m]);
    float muf  = st[1152 + m] * CNT_INV;
    float varf = fmaf(-muf, muf, st[1408 + m] * CNT_INV);
    float af   = gf[m] * rsqrtf(varf + EPS);
    float cf   = fmaf(-muf, af, bnf[m]);

    float4 o4 = *reinterpret_cast<const float4*>(rawO + e);
    float4 f4 = *reinterpret_cast<const float4*>(rawF + e);
    float4 ft = *reinterpret_cast<const float4*>(feats + e);
    float4 mk = *reinterpret_cast<const float4*>(mask + (size_t)b * NVC + col);

    float4 r;
    r.x = ft.x + (mk.x > 0.0f ? fmaxf(fmaf(o4.x, ao, co), 0.0f) + fmaxf(fmaf(f4.x, af, cf), 0.0f) : 0.0f);
    r.y = ft.y + (mk.y > 0.0f ? fmaxf(fmaf(o4.y, ao, co), 0.0f) + fmaxf(fmaf(f4.y, af, cf), 0.0f) : 0.0f);
    r.z = ft.z + (mk.z > 0.0f ? fmaxf(fmaf(o4.z, ao, co), 0.0f) + fmaxf(fmaf(f4.z, af, cf), 0.0f) : 0.0f);
    r.w = ft.w + (mk.w > 0.0f ? fmaxf(fmaf(o4.w, ao, co), 0.0f) + fmaxf(fmaf(f4.w, af, cf), 0.0f) : 0.0f);
    *reinterpret_cast<float4*>(out + e) = r;
}

extern "C" void kernel_launch(void* const* d_in, const int* in_sizes, int n_in,
                              void* d_out, int out_size)
{
    const float* feats = (const float*)d_in[0];
    const float* mask  = (const float*)d_in[1];
    const float* We    = (const float*)d_in[2];
    const float* be    = (const float*)d_in[3];
    const float* ge    = (const float*)d_in[4];
    const float* bne   = (const float*)d_in[5];
    const float* Wa    = (const float*)d_in[6];
    const float* ba    = (const float*)d_in[7];
    const float* ga    = (const float*)d_in[8];
    const float* bna   = (const float*)d_in[9];
    const float* Wo    = (const float*)d_in[10];
    const float* bo    = (const float*)d_in[11];
    const float* go    = (const float*)d_in[12];
    const float* bno   = (const float*)d_in[13];
    const float* Wf    = (const float*)d_in[14];
    const float* bf    = (const float*)d_in[15];
    const float* gf    = (const float*)d_in[16];
    const float* bnf   = (const float*)d_in[17];
    float* out = (float*)d_out;

    float *emb, *bufa, *bufb, *st;
    __nv_bfloat16 *whi, *wlo;
    cudaGetSymbolAddress((void**)&emb,  g_emb);
    cudaGetSymbolAddress((void**)&bufa, g_bufa);
    cudaGetSymbolAddress((void**)&bufb, g_bufb);
    cudaGetSymbolAddress((void**)&st,   g_stats);
    cudaGetSymbolAddress((void**)&whi,  g_whi);
    cudaGetSymbolAddress((void**)&wlo,  g_wlo);

    constexpr int SM1 = SmemCfg<64, 256>::TOTAL;
    constexpr int SM2 = SmemCfg<128, 64>::TOTAL;
    constexpr int SM3 = SmemCfg<128, 256>::TOTAL;
    cudaFuncSetAttribute(mma_layer<64, 256, 64, 0>,
                         cudaFuncAttributeMaxDynamicSharedMemorySize, SM1);
    cudaFuncSetAttribute(mma_layer<256, 64, 128, 1>,
                         cudaFuncAttributeMaxDynamicSharedMemorySize, SM2);
    cudaFuncSetAttribute(mma_layer<256, 256, 128, 1>,
                         cudaFuncAttributeMaxDynamicSharedMemorySize, SM3);
    cudaFuncSetAttribute(mma_layer<256, 256, 128, 2>,
                         cudaFuncAttributeMaxDynamicSharedMemorySize, SM3);

    zero_stats<<<8, 256>>>();
    split_weights<<<640, 256>>>(We, Wa, Wo, Wf);

    // L1 (e): rawE = We @ feats + be, masked
    mma_layer<64, 256, 64, 0><<<PGRID, 256, SM1>>>(
        feats, whi + WOFF_E, wlo + WOFF_E, be, mask,
        nullptr, nullptr, nullptr, nullptr, nullptr,
        emb, st + 0, st + 64);

    // L2 (v-slice of a): X = bn_e(rawE); rawV = Wa_v @ X + ba_v, masked
    mma_layer<256, 64, 128, 1><<<PGRID, 256, SM2>>>(
        emb, whi + WOFF_A, wlo + WOFF_A, ba + 512, mask,
        st + 0, st + 64, ge, bne, nullptr,
        bufa, st + 128, st + 384);

    // L3 (o): X = bn_v(rawV); rawO = Wo @ X + bo, masked
    mma_layer<256, 256, 128, 1><<<PGRID, 256, SM3>>>(
        bufa, whi + WOFF_O, wlo + WOFF_O, bo, mask,
        st + 128, st + 384, ga + 512, bna + 512, nullptr,
        bufb, st + 640, st + 896);

    // L4 (f): X = feats + bn_o(rawO); rawF = Wf @ X + bf, masked
    mma_layer<256, 256, 128, 2><<<PGRID, 256, SM3>>>(
        bufb, whi + WOFF_F, wlo + WOFF_F, bf, mask,
        st + 640, st + 896, go, bno, feats,
        bufa, st + 1152, st + 1408);

    // out = feats + bn_o(rawO) + bn_f(rawF)
    final_fuse<<<(NB * 256 * NVC / 4 + 255) / 256, 256>>>(
        bufb, bufa, feats, mask, st, go, bno, gf, bnf, out);
}

// round 15
// speedup vs baseline: 1.1332x; 1.1332x over previous
#include <cuda_runtime.h>
#include <cuda_fp16.h>
#include <cstdint>

// Shapes: B=8, C=256, N=1024, V=12. NVC = N*V = 12288.
// Identity: attention output == v (softmax over j sums to 1; j only indexes attn),
// so the net is 4 masked-batchstat-BN 1x1 convs (GEMMs) + residuals.
// Round 15: fp16 2-term split. Weights pre-split into fp16 hi/lo (A exact to
// 2^-22); activations single fp16 (error ~2^-11 -> rel_err ~3e-4, gate 1e-3).
// D = Ah*B + Al*B. MMAs/chunk 96->64, B smem/LDSM/STS halved.

#define NVC 12288
#define NB 8
#define CNT_INV (1.0f/98304.0f)
#define EPS 1e-5f
#define PGRID 296

__device__ float g_emb[NB * 64 * NVC];
__device__ float g_bufa[NB * 256 * NVC];
__device__ float g_bufb[NB * 256 * NVC];
__device__ float g_stats[2048];
__device__ __half g_whi[163840];
__device__ __half g_wlo[163840];

#define WOFF_E  0
#define WOFF_A  16384
#define WOFF_O  32768
#define WOFF_F  98304

__global__ void zero_stats() {
    int i = blockIdx.x * blockDim.x + threadIdx.x;
    if (i < 2048) g_stats[i] = 0.0f;
}

__global__ void split_weights(const float* __restrict__ We, const float* __restrict__ Wa,
                              const float* __restrict__ Wo, const float* __restrict__ Wf)
{
    int i = blockIdx.x * blockDim.x + threadIdx.x;
    if (i >= 163840) return;
    float w;
    if (i < 16384)       w = We[i];
    else if (i < 32768)  w = Wa[512 * 64 + (i - 16384)];
    else if (i < 98304)  w = Wo[i - 32768];
    else                 w = Wf[i - 98304];
    __half h = __float2half_rn(w);
    g_whi[i] = h;
    g_wlo[i] = __float2half_rn(w - __half2float(h));
}

__device__ __forceinline__ uint32_t smem_u32(const void* p) {
    uint32_t a;
    asm("{ .reg .u64 t; cvta.to.shared.u64 t, %1; cvt.u32.u64 %0, t; }" : "=r"(a) : "l"(p));
    return a;
}
__device__ __forceinline__ void cp_async16(uint32_t dst, const void* src) {
    asm volatile("cp.async.cg.shared.global [%0], [%1], 16;" :: "r"(dst), "l"(src));
}
#define CP_COMMIT() asm volatile("cp.async.commit_group;" ::: "memory")
#define CP_WAIT0()  asm volatile("cp.async.wait_group 0;" ::: "memory")

#define LDSM_X4(r0, r1, r2, r3, addr) \
    asm volatile("ldmatrix.sync.aligned.m8n8.x4.shared.b16 {%0,%1,%2,%3}, [%4];" \
        : "=r"(r0), "=r"(r1), "=r"(r2), "=r"(r3) : "r"(addr))
#define LDSM_X4T(r0, r1, r2, r3, addr) \
    asm volatile("ldmatrix.sync.aligned.m8n8.x4.trans.shared.b16 {%0,%1,%2,%3}, [%4];" \
        : "=r"(r0), "=r"(r1), "=r"(r2), "=r"(r3) : "r"(addr))

__device__ __forceinline__ void mma16816(float* d, const uint32_t* a, const uint32_t* b) {
    asm volatile("mma.sync.aligned.m16n8k16.row.col.f32.f16.f16.f32 "
        "{%0,%1,%2,%3}, {%4,%5,%6,%7}, {%8,%9}, {%0,%1,%2,%3};"
        : "+f"(d[0]), "+f"(d[1]), "+f"(d[2]), "+f"(d[3])
        : "r"(a[0]), "r"(a[1]), "r"(a[2]), "r"(a[3]), "r"(b[0]), "r"(b[1]));
}

// convert float4 -> 4 fp16 packed in uint2
__device__ __forceinline__ uint2 cvt4h(float4 v) {
    __half2 h01 = __floats2half2_rn(v.x, v.y);
    __half2 h23 = __floats2half2_rn(v.z, v.w);
    uint2 u;
    u.x = *reinterpret_cast<uint32_t*>(&h01);
    u.y = *reinterpret_cast<uint32_t*>(&h23);
    return u;
}

// smem layout helper (bytes)
template<int BM, int K>
struct SmemCfg {
    static constexpr int BN = 128, BK = 32, SA = 40, SB = 136;
    static constexpr int XRAW = 2 * BK * BN * 4;
    static constexpr int APL  = 2 * BM * SA * 2;   // per plane (hi/lo), 2 bufs
    static constexpr int BPL  = BK * SB * 2;       // single plane
    static constexpr int O_AH = XRAW;
    static constexpr int O_AL = O_AH + APL;
    static constexpr int O_BQ = O_AL + APL;
    static constexpr int O_MK = O_BQ + BPL;
    static constexpr int O_AS = O_MK + BN * 4;
    static constexpr int O_CS = O_AS + K * 4;
    static constexpr int O_RS = O_CS + K * 4;
    static constexpr int O_RQ = O_RS + BM * 4;
    static constexpr int TOTAL = O_RQ + BM * 4;
};

// Persistent layer kernel: grid = PGRID CTAs loop over all tiles.
// Y[b,m,col] = (sum_k W[m,k]*g(X)[b,k,col] + bias[m]) * mask, + per-channel stats.
// g(): MODE 0=identity, 1=BN+relu+mask, 2=that+resid.
template<int M, int K, int BM, int MODE>
__global__ void __launch_bounds__(256, 2)
mma_layer(const float* __restrict__ X,
          const __half* __restrict__ Whi, const __half* __restrict__ Wlo,
          const float* __restrict__ bias, const float* __restrict__ mask,
          const float* __restrict__ pssum, const float* __restrict__ pssq,
          const float* __restrict__ pg, const float* __restrict__ pb,
          const float* __restrict__ resid,
          float* __restrict__ Y, float* __restrict__ ssum, float* __restrict__ ssq)
{
    using CFG = SmemCfg<BM, K>;
    constexpr int BN = 128, BK = 32, SA = 40, SB = 136;
    constexpr int WM = BM / 2;
    constexpr int MTI = WM / 16;
    constexpr int NCH = K / BK;
    constexpr int ACP = BM * BK / 8 / 256;
    constexpr int TX = NVC / BN;
    constexpr int TY = M / BM;
    constexpr int NT = TX * TY * NB;

    extern __shared__ char sm[];
    float* Xraw = reinterpret_cast<float*>(sm);
    __half* Ah = reinterpret_cast<__half*>(sm + CFG::O_AH);
    __half* Al = reinterpret_cast<__half*>(sm + CFG::O_AL);
    __half* Bq = reinterpret_cast<__half*>(sm + CFG::O_BQ);
    float* maskS = reinterpret_cast<float*>(sm + CFG::O_MK);
    float* aS    = reinterpret_cast<float*>(sm + CFG::O_AS);
    float* cS    = reinterpret_cast<float*>(sm + CFG::O_CS);
    float* rs    = reinterpret_cast<float*>(sm + CFG::O_RS);
    float* rq    = reinterpret_cast<float*>(sm + CFG::O_RQ);

    const int tid = threadIdx.x, wid = tid >> 5, lid = tid & 31;
    const int warp_m = wid >> 2, warp_n = wid & 3;
    const int g = lid >> 2, t4 = lid & 3;
    const int lq = lid >> 3, lr = lid & 7;

    const uint32_t xrS = smem_u32(Xraw);
    const uint32_t ahS = smem_u32(Ah);
    const uint32_t alS = smem_u32(Al);

    if (MODE != 0) {
        for (int k = tid; k < K; k += 256) {
            float mu  = pssum[k] * CNT_INV;
            float var = fmaf(-mu, mu, pssq[k] * CNT_INV);
            float a   = pg[k] * rsqrtf(var + EPS);
            aS[k] = a;
            cS[k] = fmaf(-mu, a, pb[k]);
        }
    }

#pragma unroll 1
    for (int tile = blockIdx.x; tile < NT; tile += PGRID) {
        const int b   = tile / (TX * TY);
        const int rem = tile % (TX * TY);
        const int row0 = (rem / TX) * BM;
        const int col0 = (rem % TX) * BN;

        const float* Xb = X + (size_t)b * K * NVC + col0;
        const float* Rb = (MODE == 2) ? resid + (size_t)b * K * NVC + col0 : nullptr;
        const float* Mb = mask + (size_t)b * NVC + col0;
        float*       Yb = Y + (size_t)b * M * NVC + col0;

        for (int i = tid; i < BN / 4; i += 256)
            reinterpret_cast<float4*>(maskS)[i] = reinterpret_cast<const float4*>(Mb)[i];
        for (int i = tid; i < BM; i += 256) { rs[i] = 0.0f; rq[i] = 0.0f; }

        float acc[MTI][4][4];
#pragma unroll
        for (int mt = 0; mt < MTI; mt++)
#pragma unroll
            for (int nt = 0; nt < 4; nt++)
#pragma unroll
                for (int r = 0; r < 4; r++) acc[mt][nt][r] = 0.0f;

        auto issue_chunk = [&](int ch) {
            const int buf = ch & 1;
            const int k0 = ch * BK;
#pragma unroll
            for (int it = 0; it < 4; it++) {
                const int idx = tid + it * 256;
                const int kk = idx >> 5;
                const int c16 = (idx & 31) * 4;
                cp_async16(xrS + (uint32_t)(buf * BK * BN + kk * BN + c16) * 4,
                           Xb + (size_t)(k0 + kk) * NVC + c16);
            }
#pragma unroll
            for (int it = 0; it < ACP; it++) {
                const int idx = tid + it * 256;
                const int m  = idx >> 2;
                const int kq = idx & 3;
                const size_t goff = (size_t)(row0 + m) * K + k0 + kq * 8;
                const uint32_t soff = (uint32_t)(buf * BM * SA + m * SA + kq * 8) * 2;
                cp_async16(ahS + soff, Whi + goff);
                cp_async16(alS + soff, Wlo + goff);
            }
            CP_COMMIT();
        };

        issue_chunk(0);
        CP_WAIT0();
        __syncthreads();

#pragma unroll 1
        for (int ch = 0; ch < NCH; ch++) {
            const int buf = ch & 1;
            const int k0 = ch * BK;

            float4 rr[4];
            if (MODE == 2) {
#pragma unroll
                for (int it = 0; it < 4; it++) {
                    const int idx = tid + it * 256;
                    const int kk = idx >> 5;
                    const int c16 = (idx & 31) * 4;
                    rr[it] = *reinterpret_cast<const float4*>(Rb + (size_t)(k0 + kk) * NVC + c16);
                }
            }
#pragma unroll
            for (int it = 0; it < 4; it++) {
                const int idx = tid + it * 256;
                const int kk = idx >> 5;
                const int c16 = (idx & 31) * 4;
                float4 v = *reinterpret_cast<const float4*>(&Xraw[buf * BK * BN + kk * BN + c16]);
                if (MODE != 0) {
                    const float a = aS[k0 + kk], cc = cS[k0 + kk];
                    float4 mk = *reinterpret_cast<const float4*>(&maskS[c16]);
                    v.x = mk.x > 0.0f ? fmaxf(fmaf(v.x, a, cc), 0.0f) : 0.0f;
                    v.y = mk.y > 0.0f ? fmaxf(fmaf(v.y, a, cc), 0.0f) : 0.0f;
                    v.z = mk.z > 0.0f ? fmaxf(fmaf(v.z, a, cc), 0.0f) : 0.0f;
                    v.w = mk.w > 0.0f ? fmaxf(fmaf(v.w, a, cc), 0.0f) : 0.0f;
                    if (MODE == 2) {
                        v.x += rr[it].x; v.y += rr[it].y; v.z += rr[it].z; v.w += rr[it].w;
                    }
                }
                *reinterpret_cast<uint2*>(&Bq[kk * SB + c16]) = cvt4h(v);
            }
            __syncthreads();

            if (ch + 1 < NCH) issue_chunk(ch + 1);

#pragma unroll
            for (int ks = 0; ks < 2; ks++) {
                const int kb = ks * 16;
                uint32_t bq[4][2];
#pragma unroll
                for (int p = 0; p < 2; p++) {
                    const int nb = warp_n * 32 + p * 16;
                    const int brow = kb + (lq & 1) * 8 + lr;
                    const int bcol = nb + (lq >> 1) * 8;
                    uint32_t r0, r1, r2, r3;
                    LDSM_X4T(r0, r1, r2, r3, smem_u32(&Bq[brow * SB + bcol]));
                    bq[2 * p][0] = r0; bq[2 * p][1] = r1;
                    bq[2 * p + 1][0] = r2; bq[2 * p + 1][1] = r3;
                }
#pragma unroll
                for (int mt = 0; mt < MTI; mt++) {
                    const int m0 = warp_m * WM + mt * 16;
                    const int arow = m0 + (lq & 1) * 8 + lr;
                    const int acol = kb + (lq >> 1) * 8;
                    uint32_t ah[4], al[4];
                    LDSM_X4(ah[0], ah[1], ah[2], ah[3],
                            smem_u32(&Ah[buf * BM * SA + arow * SA + acol]));
                    LDSM_X4(al[0], al[1], al[2], al[3],
                            smem_u32(&Al[buf * BM * SA + arow * SA + acol]));
#pragma unroll
                    for (int nt = 0; nt < 4; nt++)
                        mma16816(acc[mt][nt], ah, bq[nt]);
#pragma unroll
                    for (int nt = 0; nt < 4; nt++)
                        mma16816(acc[mt][nt], al, bq[nt]);
                }
            }
            if (ch + 1 < NCH) CP_WAIT0();
            __syncthreads();
        }

        // ---- epilogue: bias + mask, store raw Y (row0 + rowl), per-row stats ----
#pragma unroll
        for (int mt = 0; mt < MTI; mt++) {
#pragma unroll
            for (int h = 0; h < 2; h++) {
                const int rowl = warp_m * WM + mt * 16 + h * 8 + g;
                const float bv = __ldg(&bias[row0 + rowl]);
                float s = 0.0f, q = 0.0f;
                float* yrow = Yb + (size_t)(row0 + rowl) * NVC;
#pragma unroll
                for (int nt = 0; nt < 4; nt++) {
                    const int coll = warp_n * 32 + nt * 8 + t4 * 2;
                    float y0 = (acc[mt][nt][h * 2 + 0] + bv) * maskS[coll];
                    float y1 = (acc[mt][nt][h * 2 + 1] + bv) * maskS[coll + 1];
                    s += y0 + y1;
                    q += y0 * y0 + y1 * y1;
                    float2 o; o.x = y0; o.y = y1;
                    *reinterpret_cast<float2*>(yrow + coll) = o;
                }
                s += __shfl_xor_sync(0xFFFFFFFF, s, 1);
                s += __shfl_xor_sync(0xFFFFFFFF, s, 2);
                q += __shfl_xor_sync(0xFFFFFFFF, q, 1);
                q += __shfl_xor_sync(0xFFFFFFFF, q, 2);
                if (t4 == 0) {
                    atomicAdd(&rs[rowl], s);
                    atomicAdd(&rq[rowl], q);
                }
            }
        }
        __syncthreads();
        for (int i = tid; i < BM; i += 256) {
            atomicAdd(&ssum[row0 + i], rs[i]);
            atomicAdd(&ssq[row0 + i], rq[i]);
        }
        __syncthreads();
    }
}

// out = feats + bnmask_o(rawO) + bnmask_f(rawF)
__global__ void __launch_bounds__(256)
final_fuse(const float* __restrict__ rawO, const float* __restrict__ rawF,
           const float* __restrict__ feats, const float* __restrict__ mask,
           const float* __restrict__ st,
           const float* __restrict__ go, const float* __restrict__ bno,
           const float* __restrict__ gf, const float* __restrict__ bnf,
           float* __restrict__ out)
{
    size_t i = (size_t)blockIdx.x * blockDim.x + threadIdx.x;
    constexpr size_t TOT4 = (size_t)NB * 256 * NVC / 4;
    if (i >= TOT4) return;
    size_t e = i * 4;
    int col = (int)(e % NVC);
    size_t bm = e / NVC;
    int m = (int)(bm % 256);
    int b = (int)(bm / 256);

    float muo  = st[640 + m] * CNT_INV;
    float varo = fmaf(-muo, muo, st[896 + m] * CNT_INV);
    float ao   = go[m] * rsqrtf(varo + EPS);
    float co   = fmaf(-muo, ao, bno[m]);
    float muf  = st[1152 + m] * CNT_INV;
    float varf = fmaf(-muf, muf, st[1408 + m] * CNT_INV);
    float af   = gf[m] * rsqrtf(varf + EPS);
    float cf   = fmaf(-muf, af, bnf[m]);

    float4 o4 = *reinterpret_cast<const float4*>(rawO + e);
    float4 f4 = *reinterpret_cast<const float4*>(rawF + e);
    float4 ft = *reinterpret_cast<const float4*>(feats + e);
    float4 mk = *reinterpret_cast<const float4*>(mask + (size_t)b * NVC + col);

    float4 r;
    r.x = ft.x + (mk.x > 0.0f ? fmaxf(fmaf(o4.x, ao, co), 0.0f) + fmaxf(fmaf(f4.x, af, cf), 0.0f) : 0.0f);
    r.y = ft.y + (mk.y > 0.0f ? fmaxf(fmaf(o4.y, ao, co), 0.0f) + fmaxf(fmaf(f4.y, af, cf), 0.0f) : 0.0f);
    r.z = ft.z + (mk.z > 0.0f ? fmaxf(fmaf(o4.z, ao, co), 0.0f) + fmaxf(fmaf(f4.z, af, cf), 0.0f) : 0.0f);
    r.w = ft.w + (mk.w > 0.0f ? fmaxf(fmaf(o4.w, ao, co), 0.0f) + fmaxf(fmaf(f4.w, af, cf), 0.0f) : 0.0f);
    *reinterpret_cast<float4*>(out + e) = r;
}

extern "C" void kernel_launch(void* const* d_in, const int* in_sizes, int n_in,
                              void* d_out, int out_size)
{
    const float* feats = (const float*)d_in[0];
    const float* mask  = (const float*)d_in[1];
    const float* We    = (const float*)d_in[2];
    const float* be    = (const float*)d_in[3];
    const float* ge    = (const float*)d_in[4];
    const float* bne   = (const float*)d_in[5];
    const float* Wa    = (const float*)d_in[6];
    const float* ba    = (const float*)d_in[7];
    const float* ga    = (const float*)d_in[8];
    const float* bna   = (const float*)d_in[9];
    const float* Wo    = (const float*)d_in[10];
    const float* bo    = (const float*)d_in[11];
    const float* go    = (const float*)d_in[12];
    const float* bno   = (const float*)d_in[13];
    const float* Wf    = (const float*)d_in[14];
    const float* bf    = (const float*)d_in[15];
    const float* gf    = (const float*)d_in[16];
    const float* bnf   = (const float*)d_in[17];
    float* out = (float*)d_out;

    float *emb, *bufa, *bufb, *st;
    __half *whi, *wlo;
    cudaGetSymbolAddress((void**)&emb,  g_emb);
    cudaGetSymbolAddress((void**)&bufa, g_bufa);
    cudaGetSymbolAddress((void**)&bufb, g_bufb);
    cudaGetSymbolAddress((void**)&st,   g_stats);
    cudaGetSymbolAddress((void**)&whi,  g_whi);
    cudaGetSymbolAddress((void**)&wlo,  g_wlo);

    constexpr int SM1 = SmemCfg<64, 256>::TOTAL;
    constexpr int SM2 = SmemCfg<128, 64>::TOTAL;
    constexpr int SM3 = SmemCfg<128, 256>::TOTAL;
    cudaFuncSetAttribute(mma_layer<64, 256, 64, 0>,
                         cudaFuncAttributeMaxDynamicSharedMemorySize, SM1);
    cudaFuncSetAttribute(mma_layer<256, 64, 128, 1>,
                         cudaFuncAttributeMaxDynamicSharedMemorySize, SM2);
    cudaFuncSetAttribute(mma_layer<256, 256, 128, 1>,
                         cudaFuncAttributeMaxDynamicSharedMemorySize, SM3);
    cudaFuncSetAttribute(mma_layer<256, 256, 128, 2>,
                         cudaFuncAttributeMaxDynamicSharedMemorySize, SM3);

    zero_stats<<<8, 256>>>();
    split_weights<<<640, 256>>>(We, Wa, Wo, Wf);

    // L1 (e): rawE = We @ feats + be, masked
    mma_layer<64, 256, 64, 0><<<PGRID, 256, SM1>>>(
        feats, whi + WOFF_E, wlo + WOFF_E, be, mask,
        nullptr, nullptr, nullptr, nullptr, nullptr,
        emb, st + 0, st + 64);

    // L2 (v-slice of a): X = bn_e(rawE); rawV = Wa_v @ X + ba_v, masked
    mma_layer<256, 64, 128, 1><<<PGRID, 256, SM2>>>(
        emb, whi + WOFF_A, wlo + WOFF_A, ba + 512, mask,
        st + 0, st + 64, ge, bne, nullptr,
        bufa, st + 128, st + 384);

    // L3 (o): X = bn_v(rawV); rawO = Wo @ X + bo, masked
    mma_layer<256, 256, 128, 1><<<PGRID, 256, SM3>>>(
        bufa, whi + WOFF_O, wlo + WOFF_O, bo, mask,
        st + 128, st + 384, ga + 512, bna + 512, nullptr,
        bufb, st + 640, st + 896);

    // L4 (f): X = feats + bn_o(rawO); rawF = Wf @ X + bf, masked
    mma_layer<256, 256, 128, 2><<<PGRID, 256, SM3>>>(
        bufb, whi + WOFF_F, wlo + WOFF_F, bf, mask,
        st + 640, st + 896, go, bno, feats,
        bufa, st + 1152, st + 1408);

    // out = feats + bn_o(rawO) + bn_f(rawF)
    final_fuse<<<(NB * 256 * NVC / 4 + 255) / 256, 256>>>(
        bufb, bufa, feats, mask, st, go, bno, gf, bnf, out);
}

// round 16
// speedup vs baseline: 1.1690x; 1.0316x over previous
#include <cuda_runtime.h>
#include <cuda_fp16.h>
#include <cstdint>

// Shapes: B=8, C=256, N=1024, V=12. NVC = N*V = 12288.
// Identity: attention output == v (softmax over j sums to 1; j only indexes attn),
// so the net is 4 masked-batchstat-BN 1x1 convs (GEMMs) + residuals.
// Round 16: r15 fp16 2-term split + fp16 ACTIVATION STORAGE: all inter-layer
// buffers (emb/rawV/rawO/rawF) stored as fp16 (consumed only through BN affine),
// halving DRAM traffic, X staging smem, transform LDS and Y-store bytes.

#define NVC 12288
#define NB 8
#define CNT_INV (1.0f/98304.0f)
#define EPS 1e-5f
#define PGRID 296

__device__ __half g_emb[NB * 64 * NVC];      // 12.6 MB
__device__ __half g_bufa[NB * 256 * NVC];    // 50.3 MB
__device__ __half g_bufb[NB * 256 * NVC];    // 50.3 MB
__device__ float g_stats[2048];
__device__ __half g_whi[163840];
__device__ __half g_wlo[163840];

#define WOFF_E  0
#define WOFF_A  16384
#define WOFF_O  32768
#define WOFF_F  98304

__global__ void zero_stats() {
    int i = blockIdx.x * blockDim.x + threadIdx.x;
    if (i < 2048) g_stats[i] = 0.0f;
}

__global__ void split_weights(const float* __restrict__ We, const float* __restrict__ Wa,
                              const float* __restrict__ Wo, const float* __restrict__ Wf)
{
    int i = blockIdx.x * blockDim.x + threadIdx.x;
    if (i >= 163840) return;
    float w;
    if (i < 16384)       w = We[i];
    else if (i < 32768)  w = Wa[512 * 64 + (i - 16384)];
    else if (i < 98304)  w = Wo[i - 32768];
    else                 w = Wf[i - 98304];
    __half h = __float2half_rn(w);
    g_whi[i] = h;
    g_wlo[i] = __float2half_rn(w - __half2float(h));
}

__device__ __forceinline__ uint32_t smem_u32(const void* p) {
    uint32_t a;
    asm("{ .reg .u64 t; cvta.to.shared.u64 t, %1; cvt.u32.u64 %0, t; }" : "=r"(a) : "l"(p));
    return a;
}
__device__ __forceinline__ void cp_async16(uint32_t dst, const void* src) {
    asm volatile("cp.async.cg.shared.global [%0], [%1], 16;" :: "r"(dst), "l"(src));
}
#define CP_COMMIT() asm volatile("cp.async.commit_group;" ::: "memory")
#define CP_WAIT0()  asm volatile("cp.async.wait_group 0;" ::: "memory")

#define LDSM_X4(r0, r1, r2, r3, addr) \
    asm volatile("ldmatrix.sync.aligned.m8n8.x4.shared.b16 {%0,%1,%2,%3}, [%4];" \
        : "=r"(r0), "=r"(r1), "=r"(r2), "=r"(r3) : "r"(addr))
#define LDSM_X4T(r0, r1, r2, r3, addr) \
    asm volatile("ldmatrix.sync.aligned.m8n8.x4.trans.shared.b16 {%0,%1,%2,%3}, [%4];" \
        : "=r"(r0), "=r"(r1), "=r"(r2), "=r"(r3) : "r"(addr))

__device__ __forceinline__ void mma16816(float* d, const uint32_t* a, const uint32_t* b) {
    asm volatile("mma.sync.aligned.m16n8k16.row.col.f32.f16.f16.f32 "
        "{%0,%1,%2,%3}, {%4,%5,%6,%7}, {%8,%9}, {%0,%1,%2,%3};"
        : "+f"(d[0]), "+f"(d[1]), "+f"(d[2]), "+f"(d[3])
        : "r"(a[0]), "r"(a[1]), "r"(a[2]), "r"(a[3]), "r"(b[0]), "r"(b[1]));
}

// smem layout helper (bytes); XSZ = sizeof(X element)
template<int BM, int K, int XSZ>
struct SmemCfg {
    static constexpr int BN = 128, BK = 32, SA = 40, SB = 136;
    static constexpr int XRAW = 2 * BK * BN * XSZ;
    static constexpr int APL  = 2 * BM * SA * 2;
    static constexpr int BPL  = BK * SB * 2;
    static constexpr int O_AH = XRAW;
    static constexpr int O_AL = O_AH + APL;
    static constexpr int O_BQ = O_AL + APL;
    static constexpr int O_MK = O_BQ + BPL;
    static constexpr int O_AS = O_MK + BN * 4;
    static constexpr int O_CS = O_AS + K * 4;
    static constexpr int O_RS = O_CS + K * 4;
    static constexpr int O_RQ = O_RS + BM * 4;
    static constexpr int TOTAL = O_RQ + BM * 4;
};

// Persistent layer kernel. XH: X stored as fp16 (else fp32).
// Y (fp16) = (sum_k W[m,k]*g(X)[b,k,col] + bias[m]) * mask, + per-channel stats.
// g(): MODE 0=identity, 1=BN+relu+mask, 2=that+resid(fp32).
template<int M, int K, int BM, int MODE, bool XH>
__global__ void __launch_bounds__(256, 2)
mma_layer(const void* __restrict__ Xv,
          const __half* __restrict__ Whi, const __half* __restrict__ Wlo,
          const float* __restrict__ bias, const float* __restrict__ mask,
          const float* __restrict__ pssum, const float* __restrict__ pssq,
          const float* __restrict__ pg, const float* __restrict__ pb,
          const float* __restrict__ resid,
          __half* __restrict__ Y, float* __restrict__ ssum, float* __restrict__ ssq)
{
    constexpr int XSZ = XH ? 2 : 4;
    using CFG = SmemCfg<BM, K, XSZ>;
    constexpr int BN = 128, BK = 32, SA = 40, SB = 136;
    constexpr int WM = BM / 2;
    constexpr int MTI = WM / 16;
    constexpr int NCH = K / BK;
    constexpr int ACP = BM * BK / 8 / 256;
    constexpr int XCP = BK * BN * XSZ / 16 / 256;   // 16B cp.async per thread
    constexpr int TX = NVC / BN;
    constexpr int TY = M / BM;
    constexpr int NT = TX * TY * NB;

    extern __shared__ char sm[];
    char*  Xraw = sm;
    __half* Ah = reinterpret_cast<__half*>(sm + CFG::O_AH);
    __half* Al = reinterpret_cast<__half*>(sm + CFG::O_AL);
    __half* Bq = reinterpret_cast<__half*>(sm + CFG::O_BQ);
    float* maskS = reinterpret_cast<float*>(sm + CFG::O_MK);
    float* aS    = reinterpret_cast<float*>(sm + CFG::O_AS);
    float* cS    = reinterpret_cast<float*>(sm + CFG::O_CS);
    float* rs    = reinterpret_cast<float*>(sm + CFG::O_RS);
    float* rq    = reinterpret_cast<float*>(sm + CFG::O_RQ);

    const int tid = threadIdx.x, wid = tid >> 5, lid = tid & 31;
    const int warp_m = wid >> 2, warp_n = wid & 3;
    const int g = lid >> 2, t4 = lid & 3;
    const int lq = lid >> 3, lr = lid & 7;

    const uint32_t xrS = smem_u32(Xraw);
    const uint32_t ahS = smem_u32(Ah);
    const uint32_t alS = smem_u32(Al);

    if (MODE != 0) {
        for (int k = tid; k < K; k += 256) {
            float mu  = pssum[k] * CNT_INV;
            float var = fmaf(-mu, mu, pssq[k] * CNT_INV);
            float a   = pg[k] * rsqrtf(var + EPS);
            aS[k] = a;
            cS[k] = fmaf(-mu, a, pb[k]);
        }
    }

#pragma unroll 1
    for (int tile = blockIdx.x; tile < NT; tile += PGRID) {
        const int b   = tile / (TX * TY);
        const int rem = tile % (TX * TY);
        const int row0 = (rem / TX) * BM;
        const int col0 = (rem % TX) * BN;

        const char*  Xb = reinterpret_cast<const char*>(Xv)
                        + ((size_t)b * K * NVC + col0) * XSZ;
        const float* Rb = (MODE == 2) ? resid + (size_t)b * K * NVC + col0 : nullptr;
        const float* Mb = mask + (size_t)b * NVC + col0;
        __half*      Yb = Y + (size_t)b * M * NVC + col0;

        for (int i = tid; i < BN / 4; i += 256)
            reinterpret_cast<float4*>(maskS)[i] = reinterpret_cast<const float4*>(Mb)[i];
        for (int i = tid; i < BM; i += 256) { rs[i] = 0.0f; rq[i] = 0.0f; }

        float acc[MTI][4][4];
#pragma unroll
        for (int mt = 0; mt < MTI; mt++)
#pragma unroll
            for (int nt = 0; nt < 4; nt++)
#pragma unroll
                for (int r = 0; r < 4; r++) acc[mt][nt][r] = 0.0f;

        auto issue_chunk = [&](int ch) {
            const int buf = ch & 1;
            const int k0 = ch * BK;
            constexpr int EPC = 16 / XSZ;           // elements per 16B copy
            constexpr int CPR = BN / EPC;           // copies per k-row
#pragma unroll
            for (int it = 0; it < XCP; it++) {
                const int idx = tid + it * 256;
                const int kk = idx / CPR;
                const int ce = (idx % CPR) * EPC;
                cp_async16(xrS + (uint32_t)((buf * BK + kk) * BN + ce) * XSZ,
                           Xb + ((size_t)(k0 + kk) * NVC + ce) * XSZ);
            }
#pragma unroll
            for (int it = 0; it < ACP; it++) {
                const int idx = tid + it * 256;
                const int m  = idx >> 2;
                const int kq = idx & 3;
                const size_t goff = (size_t)(row0 + m) * K + k0 + kq * 8;
                const uint32_t soff = (uint32_t)(buf * BM * SA + m * SA + kq * 8) * 2;
                cp_async16(ahS + soff, Whi + goff);
                cp_async16(alS + soff, Wlo + goff);
            }
            CP_COMMIT();
        };

        issue_chunk(0);
        CP_WAIT0();
        __syncthreads();

#pragma unroll 1
        for (int ch = 0; ch < NCH; ch++) {
            const int buf = ch & 1;
            const int k0 = ch * BK;

            // ---- transform: Xraw[buf] -> Bq fp16 tile ----
            if (XH) {
                // 2 iters x 8 halves per thread
                float4 rr[2][2];
                if (MODE == 2) {
#pragma unroll
                    for (int it = 0; it < 2; it++) {
                        const int idx = tid + it * 256;
                        const int kk = idx >> 4;
                        const int c8 = (idx & 15) * 8;
                        rr[it][0] = *reinterpret_cast<const float4*>(Rb + (size_t)(k0 + kk) * NVC + c8);
                        rr[it][1] = *reinterpret_cast<const float4*>(Rb + (size_t)(k0 + kk) * NVC + c8 + 4);
                    }
                }
#pragma unroll
                for (int it = 0; it < 2; it++) {
                    const int idx = tid + it * 256;
                    const int kk = idx >> 4;
                    const int c8 = (idx & 15) * 8;
                    uint4 raw = *reinterpret_cast<const uint4*>(
                        Xraw + (size_t)((buf * BK + kk) * BN + c8) * 2);
                    const __half2* hp = reinterpret_cast<const __half2*>(&raw);
                    float xv[8];
#pragma unroll
                    for (int j = 0; j < 4; j++) {
                        float2 f = __half22float2(hp[j]);
                        xv[2 * j] = f.x; xv[2 * j + 1] = f.y;
                    }
                    if (MODE != 0) {
                        const float a = aS[k0 + kk], cc = cS[k0 + kk];
#pragma unroll
                        for (int j = 0; j < 8; j++) {
                            float m = maskS[c8 + j];
                            float y = m > 0.0f ? fmaxf(fmaf(xv[j], a, cc), 0.0f) : 0.0f;
                            if (MODE == 2)
                                y += reinterpret_cast<const float*>(&rr[it][0])[j];
                            xv[j] = y;
                        }
                    }
                    uint4 out;
                    __half2* op = reinterpret_cast<__half2*>(&out);
#pragma unroll
                    for (int j = 0; j < 4; j++)
                        op[j] = __floats2half2_rn(xv[2 * j], xv[2 * j + 1]);
                    *reinterpret_cast<uint4*>(&Bq[kk * SB + c8]) = out;
                }
            } else {
                // fp32 input: 4 iters x 4 floats per thread
                float4 rr[4];
                if (MODE == 2) {
#pragma unroll
                    for (int it = 0; it < 4; it++) {
                        const int idx = tid + it * 256;
                        const int kk = idx >> 5;
                        const int c4 = (idx & 31) * 4;
                        rr[it] = *reinterpret_cast<const float4*>(Rb + (size_t)(k0 + kk) * NVC + c4);
                    }
                }
#pragma unroll
                for (int it = 0; it < 4; it++) {
                    const int idx = tid + it * 256;
                    const int kk = idx >> 5;
                    const int c4 = (idx & 31) * 4;
                    float4 v = *reinterpret_cast<const float4*>(
                        Xraw + (size_t)((buf * BK + kk) * BN + c4) * 4);
                    if (MODE != 0) {
                        const float a = aS[k0 + kk], cc = cS[k0 + kk];
                        float4 mk = *reinterpret_cast<const float4*>(&maskS[c4]);
                        v.x = mk.x > 0.0f ? fmaxf(fmaf(v.x, a, cc), 0.0f) : 0.0f;
                        v.y = mk.y > 0.0f ? fmaxf(fmaf(v.y, a, cc), 0.0f) : 0.0f;
                        v.z = mk.z > 0.0f ? fmaxf(fmaf(v.z, a, cc), 0.0f) : 0.0f;
                        v.w = mk.w > 0.0f ? fmaxf(fmaf(v.w, a, cc), 0.0f) : 0.0f;
                        if (MODE == 2) {
                            v.x += rr[it].x; v.y += rr[it].y; v.z += rr[it].z; v.w += rr[it].w;
                        }
                    }
                    uint2 u;
                    __half2 h01 = __floats2half2_rn(v.x, v.y);
                    __half2 h23 = __floats2half2_rn(v.z, v.w);
                    u.x = *reinterpret_cast<uint32_t*>(&h01);
                    u.y = *reinterpret_cast<uint32_t*>(&h23);
                    *reinterpret_cast<uint2*>(&Bq[kk * SB + c4]) = u;
                }
            }
            __syncthreads();

            if (ch + 1 < NCH) issue_chunk(ch + 1);

#pragma unroll
            for (int ks = 0; ks < 2; ks++) {
                const int kb = ks * 16;
                uint32_t bq[4][2];
#pragma unroll
                for (int p = 0; p < 2; p++) {
                    const int nb = warp_n * 32 + p * 16;
                    const int brow = kb + (lq & 1) * 8 + lr;
                    const int bcol = nb + (lq >> 1) * 8;
                    uint32_t r0, r1, r2, r3;
                    LDSM_X4T(r0, r1, r2, r3, smem_u32(&Bq[brow * SB + bcol]));
                    bq[2 * p][0] = r0; bq[2 * p][1] = r1;
                    bq[2 * p + 1][0] = r2; bq[2 * p + 1][1] = r3;
                }
#pragma unroll
                for (int mt = 0; mt < MTI; mt++) {
                    const int m0 = warp_m * WM + mt * 16;
                    const int arow = m0 + (lq & 1) * 8 + lr;
                    const int acol = kb + (lq >> 1) * 8;
                    uint32_t ah[4], al[4];
                    LDSM_X4(ah[0], ah[1], ah[2], ah[3],
                            smem_u32(&Ah[buf * BM * SA + arow * SA + acol]));
                    LDSM_X4(al[0], al[1], al[2], al[3],
                            smem_u32(&Al[buf * BM * SA + arow * SA + acol]));
#pragma unroll
                    for (int nt = 0; nt < 4; nt++)
                        mma16816(acc[mt][nt], ah, bq[nt]);
#pragma unroll
                    for (int nt = 0; nt < 4; nt++)
                        mma16816(acc[mt][nt], al, bq[nt]);
                }
            }
            if (ch + 1 < NCH) CP_WAIT0();
            __syncthreads();
        }

        // ---- epilogue: bias + mask, store Y fp16 (row0 + rowl), per-row stats ----
#pragma unroll
        for (int mt = 0; mt < MTI; mt++) {
#pragma unroll
            for (int h = 0; h < 2; h++) {
                const int rowl = warp_m * WM + mt * 16 + h * 8 + g;
                const float bv = __ldg(&bias[row0 + rowl]);
                float s = 0.0f, q = 0.0f;
                __half* yrow = Yb + (size_t)(row0 + rowl) * NVC;
#pragma unroll
                for (int nt = 0; nt < 4; nt++) {
                    const int coll = warp_n * 32 + nt * 8 + t4 * 2;
                    float y0 = (acc[mt][nt][h * 2 + 0] + bv) * maskS[coll];
                    float y1 = (acc[mt][nt][h * 2 + 1] + bv) * maskS[coll + 1];
                    s += y0 + y1;
                    q += y0 * y0 + y1 * y1;
                    *reinterpret_cast<__half2*>(yrow + coll) = __floats2half2_rn(y0, y1);
                }
                s += __shfl_xor_sync(0xFFFFFFFF, s, 1);
                s += __shfl_xor_sync(0xFFFFFFFF, s, 2);
                q += __shfl_xor_sync(0xFFFFFFFF, q, 1);
                q += __shfl_xor_sync(0xFFFFFFFF, q, 2);
                if (t4 == 0) {
                    atomicAdd(&rs[rowl], s);
                    atomicAdd(&rq[rowl], q);
                }
            }
        }
        __syncthreads();
        for (int i = tid; i < BM; i += 256) {
            atomicAdd(&ssum[row0 + i], rs[i]);
            atomicAdd(&ssq[row0 + i], rq[i]);
        }
        __syncthreads();
    }
}

// out = feats + bnmask_o(rawO) + bnmask_f(rawF)   (rawO/rawF fp16)
__global__ void __launch_bounds__(256)
final_fuse(const __half* __restrict__ rawO, const __half* __restrict__ rawF,
           const float* __restrict__ feats, const float* __restrict__ mask,
           const float* __restrict__ st,
           const float* __restrict__ go, const float* __restrict__ bno,
           const float* __restrict__ gf, const float* __restrict__ bnf,
           float* __restrict__ out)
{
    size_t i = (size_t)blockIdx.x * blockDim.x + threadIdx.x;
    constexpr size_t TOT4 = (size_t)NB * 256 * NVC / 4;
    if (i >= TOT4) return;
    size_t e = i * 4;
    int col = (int)(e % NVC);
    size_t bm = e / NVC;
    int m = (int)(bm % 256);
    int b = (int)(bm / 256);

    float muo  = st[640 + m] * CNT_INV;
    float varo = fmaf(-muo, muo, st[896 + m] * CNT_INV);
    float ao   = go[m] * rsqrtf(varo + EPS);
    float co   = fmaf(-muo, ao, bno[m]);
    float muf  = st[1152 + m] * CNT_INV;
    float varf = fmaf(-muf, muf, st[1408 + m] * CNT_INV);
    float af   = gf[m] * rsqrtf(varf + EPS);
    float cf   = fmaf(-muf, af, bnf[m]);

    uint2 oh = *reinterpret_cast<const uint2*>(rawO + e);
    uint2 fh = *reinterpret_cast<const uint2*>(rawF + e);
    const __half2* op = reinterpret_cast<const __half2*>(&oh);
    const __half2* fp = reinterpret_cast<const __half2*>(&fh);
    float2 o01 = __half22float2(op[0]), o23 = __half22float2(op[1]);
    float2 f01 = __half22float2(fp[0]), f23 = __half22float2(fp[1]);

    float4 ft = *reinterpret_cast<const float4*>(feats + e);
    float4 mk = *reinterpret_cast<const float4*>(mask + (size_t)b * NVC + col);

    float4 r;
    r.x = ft.x + (mk.x > 0.0f ? fmaxf(fmaf(o01.x, ao, co), 0.0f) + fmaxf(fmaf(f01.x, af, cf), 0.0f) : 0.0f);
    r.y = ft.y + (mk.y > 0.0f ? fmaxf(fmaf(o01.y, ao, co), 0.0f) + fmaxf(fmaf(f01.y, af, cf), 0.0f) : 0.0f);
    r.z = ft.z + (mk.z > 0.0f ? fmaxf(fmaf(o23.x, ao, co), 0.0f) + fmaxf(fmaf(f23.x, af, cf), 0.0f) : 0.0f);
    r.w = ft.w + (mk.w > 0.0f ? fmaxf(fmaf(o23.y, ao, co), 0.0f) + fmaxf(fmaf(f23.y, af, cf), 0.0f) : 0.0f);
    *reinterpret_cast<float4*>(out + e) = r;
}

extern "C" void kernel_launch(void* const* d_in, const int* in_sizes, int n_in,
                              void* d_out, int out_size)
{
    const float* feats = (const float*)d_in[0];
    const float* mask  = (const float*)d_in[1];
    const float* We    = (const float*)d_in[2];
    const float* be    = (const float*)d_in[3];
    const float* ge    = (const float*)d_in[4];
    const float* bne   = (const float*)d_in[5];
    const float* Wa    = (const float*)d_in[6];
    const float* ba    = (const float*)d_in[7];
    const float* ga    = (const float*)d_in[8];
    const float* bna   = (const float*)d_in[9];
    const float* Wo    = (const float*)d_in[10];
    const float* bo    = (const float*)d_in[11];
    const float* go    = (const float*)d_in[12];
    const float* bno   = (const float*)d_in[13];
    const float* Wf    = (const float*)d_in[14];
    const float* bf    = (const float*)d_in[15];
    const float* gf    = (const float*)d_in[16];
    const float* bnf   = (const float*)d_in[17];
    float* out = (float*)d_out;

    float *st;
    __half *emb, *bufa, *bufb, *whi, *wlo;
    cudaGetSymbolAddress((void**)&emb,  g_emb);
    cudaGetSymbolAddress((void**)&bufa, g_bufa);
    cudaGetSymbolAddress((void**)&bufb, g_bufb);
    cudaGetSymbolAddress((void**)&st,   g_stats);
    cudaGetSymbolAddress((void**)&whi,  g_whi);
    cudaGetSymbolAddress((void**)&wlo,  g_wlo);

    constexpr int SM1 = SmemCfg<64, 256, 4>::TOTAL;
    constexpr int SM2 = SmemCfg<128, 64, 2>::TOTAL;
    constexpr int SM3 = SmemCfg<128, 256, 2>::TOTAL;
    cudaFuncSetAttribute(mma_layer<64, 256, 64, 0, false>,
                         cudaFuncAttributeMaxDynamicSharedMemorySize, SM1);
    cudaFuncSetAttribute(mma_layer<256, 64, 128, 1, true>,
                         cudaFuncAttributeMaxDynamicSharedMemorySize, SM2);
    cudaFuncSetAttribute(mma_layer<256, 256, 128, 1, true>,
                         cudaFuncAttributeMaxDynamicSharedMemorySize, SM3);
    cudaFuncSetAttribute(mma_layer<256, 256, 128, 2, true>,
                         cudaFuncAttributeMaxDynamicSharedMemorySize, SM3);

    zero_stats<<<8, 256>>>();
    split_weights<<<640, 256>>>(We, Wa, Wo, Wf);

    // L1 (e): rawE(fp16) = We @ feats(fp32) + be, masked
    mma_layer<64, 256, 64, 0, false><<<PGRID, 256, SM1>>>(
        feats, whi + WOFF_E, wlo + WOFF_E, be, mask,
        nullptr, nullptr, nullptr, nullptr, nullptr,
        emb, st + 0, st + 64);

    // L2 (v-slice of a): X = bn_e(rawE); rawV(fp16) = Wa_v @ X + ba_v, masked
    mma_layer<256, 64, 128, 1, true><<<PGRID, 256, SM2>>>(
        emb, whi + WOFF_A, wlo + WOFF_A, ba + 512, mask,
        st + 0, st + 64, ge, bne, nullptr,
        bufa, st + 128, st + 384);

    // L3 (o): X = bn_v(rawV); rawO(fp16) = Wo @ X + bo, masked
    mma_layer<256, 256, 128, 1, true><<<PGRID, 256, SM3>>>(
        bufa, whi + WOFF_O, wlo + WOFF_O, bo, mask,
        st + 128, st + 384, ga + 512, bna + 512, nullptr,
        bufb, st + 640, st + 896);

    // L4 (f): X = feats + bn_o(rawO); rawF(fp16) = Wf @ X + bf, masked
    mma_layer<256, 256, 128, 2, true><<<PGRID, 256, SM3>>>(
        bufb, whi + WOFF_F, wlo + WOFF_F, bf, mask,
        st + 640, st + 896, go, bno, feats,
        bufa, st + 1152, st + 1408);

    // out = feats + bn_o(rawO) + bn_f(rawF)
    final_fuse<<<(NB * 256 * NVC / 4 + 255) / 256, 256>>>(
        bufb, bufa, feats, mask, st, go, bno, gf, bnf, out);
}

// round 17
// speedup vs baseline: 1.3697x; 1.1717x over previous
#include <cuda_runtime.h>
#include <cuda_fp16.h>
#include <cstdint>

// Shapes: B=8, C=256, N=1024, V=12. NVC = N*V = 12288.
// Identity: attention output == v (softmax over j sums to 1; j only indexes attn),
// so the net is 4 masked-batchstat-BN 1x1 convs (GEMMs) + residuals.
// Round 17: single fp16 weights (drop Al split term). MMAs/chunk 64->32,
// A smem/cp.async/LDSM halved. fp16 activations end-to-end (r16).
// Error budget: +1 fp16 quant source per layer -> predicted rel_err ~5.5e-4.

#define NVC 12288
#define NB 8
#define CNT_INV (1.0f/98304.0f)
#define EPS 1e-5f
#define PGRID 296

__device__ __half g_emb[NB * 64 * NVC];
__device__ __half g_bufa[NB * 256 * NVC];
__device__ __half g_bufb[NB * 256 * NVC];
__device__ float g_stats[2048];
__device__ __half g_whi[163840];

#define WOFF_E  0
#define WOFF_A  16384
#define WOFF_O  32768
#define WOFF_F  98304

__global__ void zero_stats() {
    int i = blockIdx.x * blockDim.x + threadIdx.x;
    if (i < 2048) g_stats[i] = 0.0f;
}

__global__ void split_weights(const float* __restrict__ We, const float* __restrict__ Wa,
                              const float* __restrict__ Wo, const float* __restrict__ Wf)
{
    int i = blockIdx.x * blockDim.x + threadIdx.x;
    if (i >= 163840) return;
    float w;
    if (i < 16384)       w = We[i];
    else if (i < 32768)  w = Wa[512 * 64 + (i - 16384)];
    else if (i < 98304)  w = Wo[i - 32768];
    else                 w = Wf[i - 98304];
    g_whi[i] = __float2half_rn(w);
}

__device__ __forceinline__ uint32_t smem_u32(const void* p) {
    uint32_t a;
    asm("{ .reg .u64 t; cvta.to.shared.u64 t, %1; cvt.u32.u64 %0, t; }" : "=r"(a) : "l"(p));
    return a;
}
__device__ __forceinline__ void cp_async16(uint32_t dst, const void* src) {
    asm volatile("cp.async.cg.shared.global [%0], [%1], 16;" :: "r"(dst), "l"(src));
}
#define CP_COMMIT() asm volatile("cp.async.commit_group;" ::: "memory")
#define CP_WAIT0()  asm volatile("cp.async.wait_group 0;" ::: "memory")

#define LDSM_X4(r0, r1, r2, r3, addr) \
    asm volatile("ldmatrix.sync.aligned.m8n8.x4.shared.b16 {%0,%1,%2,%3}, [%4];" \
        : "=r"(r0), "=r"(r1), "=r"(r2), "=r"(r3) : "r"(addr))
#define LDSM_X4T(r0, r1, r2, r3, addr) \
    asm volatile("ldmatrix.sync.aligned.m8n8.x4.trans.shared.b16 {%0,%1,%2,%3}, [%4];" \
        : "=r"(r0), "=r"(r1), "=r"(r2), "=r"(r3) : "r"(addr))

__device__ __forceinline__ void mma16816(float* d, const uint32_t* a, const uint32_t* b) {
    asm volatile("mma.sync.aligned.m16n8k16.row.col.f32.f16.f16.f32 "
        "{%0,%1,%2,%3}, {%4,%5,%6,%7}, {%8,%9}, {%0,%1,%2,%3};"
        : "+f"(d[0]), "+f"(d[1]), "+f"(d[2]), "+f"(d[3])
        : "r"(a[0]), "r"(a[1]), "r"(a[2]), "r"(a[3]), "r"(b[0]), "r"(b[1]));
}

// smem layout helper (bytes); XSZ = sizeof(X element)
template<int BM, int K, int XSZ>
struct SmemCfg {
    static constexpr int BN = 128, BK = 32, SA = 40, SB = 136;
    static constexpr int XRAW = 2 * BK * BN * XSZ;
    static constexpr int APL  = 2 * BM * SA * 2;   // single plane, 2 bufs
    static constexpr int BPL  = BK * SB * 2;
    static constexpr int O_AH = XRAW;
    static constexpr int O_BQ = O_AH + APL;
    static constexpr int O_MK = O_BQ + BPL;
    static constexpr int O_AS = O_MK + BN * 4;
    static constexpr int O_CS = O_AS + K * 4;
    static constexpr int O_RS = O_CS + K * 4;
    static constexpr int O_RQ = O_RS + BM * 4;
    static constexpr int TOTAL = O_RQ + BM * 4;
};

// Persistent layer kernel. XH: X stored fp16 (else fp32).
// Y (fp16) = (sum_k W[m,k]*g(X)[b,k,col] + bias[m]) * mask, + per-channel stats.
// g(): MODE 0=identity, 1=BN+relu+mask, 2=that+resid(fp32).
template<int M, int K, int BM, int MODE, bool XH>
__global__ void __launch_bounds__(256, 2)
mma_layer(const void* __restrict__ Xv,
          const __half* __restrict__ Whi,
          const float* __restrict__ bias, const float* __restrict__ mask,
          const float* __restrict__ pssum, const float* __restrict__ pssq,
          const float* __restrict__ pg, const float* __restrict__ pb,
          const float* __restrict__ resid,
          __half* __restrict__ Y, float* __restrict__ ssum, float* __restrict__ ssq)
{
    constexpr int XSZ = XH ? 2 : 4;
    using CFG = SmemCfg<BM, K, XSZ>;
    constexpr int BN = 128, BK = 32, SA = 40, SB = 136;
    constexpr int WM = BM / 2;
    constexpr int MTI = WM / 16;
    constexpr int NCH = K / BK;
    constexpr int ACP = BM * BK / 8 / 256;
    constexpr int XCP = BK * BN * XSZ / 16 / 256;
    constexpr int TX = NVC / BN;
    constexpr int TY = M / BM;
    constexpr int NT = TX * TY * NB;

    extern __shared__ char sm[];
    char*  Xraw = sm;
    __half* Ah = reinterpret_cast<__half*>(sm + CFG::O_AH);
    __half* Bq = reinterpret_cast<__half*>(sm + CFG::O_BQ);
    float* maskS = reinterpret_cast<float*>(sm + CFG::O_MK);
    float* aS    = reinterpret_cast<float*>(sm + CFG::O_AS);
    float* cS    = reinterpret_cast<float*>(sm + CFG::O_CS);
    float* rs    = reinterpret_cast<float*>(sm + CFG::O_RS);
    float* rq    = reinterpret_cast<float*>(sm + CFG::O_RQ);

    const int tid = threadIdx.x, wid = tid >> 5, lid = tid & 31;
    const int warp_m = wid >> 2, warp_n = wid & 3;
    const int g = lid >> 2, t4 = lid & 3;
    const int lq = lid >> 3, lr = lid & 7;

    const uint32_t xrS = smem_u32(Xraw);
    const uint32_t ahS = smem_u32(Ah);

    if (MODE != 0) {
        for (int k = tid; k < K; k += 256) {
            float mu  = pssum[k] * CNT_INV;
            float var = fmaf(-mu, mu, pssq[k] * CNT_INV);
            float a   = pg[k] * rsqrtf(var + EPS);
            aS[k] = a;
            cS[k] = fmaf(-mu, a, pb[k]);
        }
    }

#pragma unroll 1
    for (int tile = blockIdx.x; tile < NT; tile += PGRID) {
        const int b   = tile / (TX * TY);
        const int rem = tile % (TX * TY);
        const int row0 = (rem / TX) * BM;
        const int col0 = (rem % TX) * BN;

        const char*  Xb = reinterpret_cast<const char*>(Xv)
                        + ((size_t)b * K * NVC + col0) * XSZ;
        const float* Rb = (MODE == 2) ? resid + (size_t)b * K * NVC + col0 : nullptr;
        const float* Mb = mask + (size_t)b * NVC + col0;
        __half*      Yb = Y + (size_t)b * M * NVC + col0;

        for (int i = tid; i < BN / 4; i += 256)
            reinterpret_cast<float4*>(maskS)[i] = reinterpret_cast<const float4*>(Mb)[i];
        for (int i = tid; i < BM; i += 256) { rs[i] = 0.0f; rq[i] = 0.0f; }

        float acc[MTI][4][4];
#pragma unroll
        for (int mt = 0; mt < MTI; mt++)
#pragma unroll
            for (int nt = 0; nt < 4; nt++)
#pragma unroll
                for (int r = 0; r < 4; r++) acc[mt][nt][r] = 0.0f;

        auto issue_chunk = [&](int ch) {
            const int buf = ch & 1;
            const int k0 = ch * BK;
            constexpr int EPC = 16 / XSZ;
            constexpr int CPR = BN / EPC;
#pragma unroll
            for (int it = 0; it < XCP; it++) {
                const int idx = tid + it * 256;
                const int kk = idx / CPR;
                const int ce = (idx % CPR) * EPC;
                cp_async16(xrS + (uint32_t)((buf * BK + kk) * BN + ce) * XSZ,
                           Xb + ((size_t)(k0 + kk) * NVC + ce) * XSZ);
            }
#pragma unroll
            for (int it = 0; it < ACP; it++) {
                const int idx = tid + it * 256;
                const int m  = idx >> 2;
                const int kq = idx & 3;
                const size_t goff = (size_t)(row0 + m) * K + k0 + kq * 8;
                const uint32_t soff = (uint32_t)(buf * BM * SA + m * SA + kq * 8) * 2;
                cp_async16(ahS + soff, Whi + goff);
            }
            CP_COMMIT();
        };

        issue_chunk(0);
        CP_WAIT0();
        __syncthreads();

#pragma unroll 1
        for (int ch = 0; ch < NCH; ch++) {
            const int buf = ch & 1;
            const int k0 = ch * BK;

            // ---- transform: Xraw[buf] -> Bq fp16 tile ----
            if (XH) {
                float4 rr[2][2];
                if (MODE == 2) {
#pragma unroll
                    for (int it = 0; it < 2; it++) {
                        const int idx = tid + it * 256;
                        const int kk = idx >> 4;
                        const int c8 = (idx & 15) * 8;
                        rr[it][0] = *reinterpret_cast<const float4*>(Rb + (size_t)(k0 + kk) * NVC + c8);
                        rr[it][1] = *reinterpret_cast<const float4*>(Rb + (size_t)(k0 + kk) * NVC + c8 + 4);
                    }
                }
#pragma unroll
                for (int it = 0; it < 2; it++) {
                    const int idx = tid + it * 256;
                    const int kk = idx >> 4;
                    const int c8 = (idx & 15) * 8;
                    uint4 raw = *reinterpret_cast<const uint4*>(
                        Xraw + (size_t)((buf * BK + kk) * BN + c8) * 2);
                    const __half2* hp = reinterpret_cast<const __half2*>(&raw);
                    float xv[8];
#pragma unroll
                    for (int j = 0; j < 4; j++) {
                        float2 f = __half22float2(hp[j]);
                        xv[2 * j] = f.x; xv[2 * j + 1] = f.y;
                    }
                    if (MODE != 0) {
                        const float a = aS[k0 + kk], cc = cS[k0 + kk];
#pragma unroll
                        for (int j = 0; j < 8; j++) {
                            float m = maskS[c8 + j];
                            float y = m > 0.0f ? fmaxf(fmaf(xv[j], a, cc), 0.0f) : 0.0f;
                            if (MODE == 2)
                                y += reinterpret_cast<const float*>(&rr[it][0])[j];
                            xv[j] = y;
                        }
                    }
                    uint4 out;
                    __half2* op = reinterpret_cast<__half2*>(&out);
#pragma unroll
                    for (int j = 0; j < 4; j++)
                        op[j] = __floats2half2_rn(xv[2 * j], xv[2 * j + 1]);
                    *reinterpret_cast<uint4*>(&Bq[kk * SB + c8]) = out;
                }
            } else {
                float4 rr[4];
                if (MODE == 2) {
#pragma unroll
                    for (int it = 0; it < 4; it++) {
                        const int idx = tid + it * 256;
                        const int kk = idx >> 5;
                        const int c4 = (idx & 31) * 4;
                        rr[it] = *reinterpret_cast<const float4*>(Rb + (size_t)(k0 + kk) * NVC + c4);
                    }
                }
#pragma unroll
                for (int it = 0; it < 4; it++) {
                    const int idx = tid + it * 256;
                    const int kk = idx >> 5;
                    const int c4 = (idx & 31) * 4;
                    float4 v = *reinterpret_cast<const float4*>(
                        Xraw + (size_t)((buf * BK + kk) * BN + c4) * 4);
                    if (MODE != 0) {
                        const float a = aS[k0 + kk], cc = cS[k0 + kk];
                        float4 mk = *reinterpret_cast<const float4*>(&maskS[c4]);
                        v.x = mk.x > 0.0f ? fmaxf(fmaf(v.x, a, cc), 0.0f) : 0.0f;
                        v.y = mk.y > 0.0f ? fmaxf(fmaf(v.y, a, cc), 0.0f) : 0.0f;
                        v.z = mk.z > 0.0f ? fmaxf(fmaf(v.z, a, cc), 0.0f) : 0.0f;
                        v.w = mk.w > 0.0f ? fmaxf(fmaf(v.w, a, cc), 0.0f) : 0.0f;
                        if (MODE == 2) {
                            v.x += rr[it].x; v.y += rr[it].y; v.z += rr[it].z; v.w += rr[it].w;
                        }
                    }
                    uint2 u;
                    __half2 h01 = __floats2half2_rn(v.x, v.y);
                    __half2 h23 = __floats2half2_rn(v.z, v.w);
                    u.x = *reinterpret_cast<uint32_t*>(&h01);
                    u.y = *reinterpret_cast<uint32_t*>(&h23);
                    *reinterpret_cast<uint2*>(&Bq[kk * SB + c4]) = u;
                }
            }
            __syncthreads();

            if (ch + 1 < NCH) issue_chunk(ch + 1);

#pragma unroll
            for (int ks = 0; ks < 2; ks++) {
                const int kb = ks * 16;
                uint32_t bq[4][2];
#pragma unroll
                for (int p = 0; p < 2; p++) {
                    const int nb = warp_n * 32 + p * 16;
                    const int brow = kb + (lq & 1) * 8 + lr;
                    const int bcol = nb + (lq >> 1) * 8;
                    uint32_t r0, r1, r2, r3;
                    LDSM_X4T(r0, r1, r2, r3, smem_u32(&Bq[brow * SB + bcol]));
                    bq[2 * p][0] = r0; bq[2 * p][1] = r1;
                    bq[2 * p + 1][0] = r2; bq[2 * p + 1][1] = r3;
                }
#pragma unroll
                for (int mt = 0; mt < MTI; mt++) {
                    const int m0 = warp_m * WM + mt * 16;
                    const int arow = m0 + (lq & 1) * 8 + lr;
                    const int acol = kb + (lq >> 1) * 8;
                    uint32_t ah[4];
                    LDSM_X4(ah[0], ah[1], ah[2], ah[3],
                            smem_u32(&Ah[buf * BM * SA + arow * SA + acol]));
#pragma unroll
                    for (int nt = 0; nt < 4; nt++)
                        mma16816(acc[mt][nt], ah, bq[nt]);
                }
            }
            if (ch + 1 < NCH) CP_WAIT0();
            __syncthreads();
        }

        // ---- epilogue: bias + mask, store Y fp16 (row0 + rowl), per-row stats ----
#pragma unroll
        for (int mt = 0; mt < MTI; mt++) {
#pragma unroll
            for (int h = 0; h < 2; h++) {
                const int rowl = warp_m * WM + mt * 16 + h * 8 + g;
                const float bv = __ldg(&bias[row0 + rowl]);
                float s = 0.0f, q = 0.0f;
                __half* yrow = Yb + (size_t)(row0 + rowl) * NVC;
#pragma unroll
                for (int nt = 0; nt < 4; nt++) {
                    const int coll = warp_n * 32 + nt * 8 + t4 * 2;
                    float y0 = (acc[mt][nt][h * 2 + 0] + bv) * maskS[coll];
                    float y1 = (acc[mt][nt][h * 2 + 1] + bv) * maskS[coll + 1];
                    s += y0 + y1;
                    q += y0 * y0 + y1 * y1;
                    *reinterpret_cast<__half2*>(yrow + coll) = __floats2half2_rn(y0, y1);
                }
                s += __shfl_xor_sync(0xFFFFFFFF, s, 1);
                s += __shfl_xor_sync(0xFFFFFFFF, s, 2);
                q += __shfl_xor_sync(0xFFFFFFFF, q, 1);
                q += __shfl_xor_sync(0xFFFFFFFF, q, 2);
                if (t4 == 0) {
                    atomicAdd(&rs[rowl], s);
                    atomicAdd(&rq[rowl], q);
                }
            }
        }
        __syncthreads();
        for (int i = tid; i < BM; i += 256) {
            atomicAdd(&ssum[row0 + i], rs[i]);
            atomicAdd(&ssq[row0 + i], rq[i]);
        }
        __syncthreads();
    }
}

// out = feats + bnmask_o(rawO) + bnmask_f(rawF)   (rawO/rawF fp16)
__global__ void __launch_bounds__(256)
final_fuse(const __half* __restrict__ rawO, const __half* __restrict__ rawF,
           const float* __restrict__ feats, const float* __restrict__ mask,
           const float* __restrict__ st,
           const float* __restrict__ go, const float* __restrict__ bno,
           const float* __restrict__ gf, const float* __restrict__ bnf,
           float* __restrict__ out)
{
    size_t i = (size_t)blockIdx.x * blockDim.x + threadIdx.x;
    constexpr size_t TOT4 = (size_t)NB * 256 * NVC / 4;
    if (i >= TOT4) return;
    size_t e = i * 4;
    int col = (int)(e % NVC);
    size_t bm = e / NVC;
    int m = (int)(bm % 256);
    int b = (int)(bm / 256);

    float muo  = st[640 + m] * CNT_INV;
    float varo = fmaf(-muo, muo, st[896 + m] * CNT_INV);
    float ao   = go[m] * rsqrtf(varo + EPS);
    float co   = fmaf(-muo, ao, bno[m]);
    float muf  = st[1152 + m] * CNT_INV;
    float varf = fmaf(-muf, muf, st[1408 + m] * CNT_INV);
    float af   = gf[m] * rsqrtf(varf + EPS);
    float cf   = fmaf(-muf, af, bnf[m]);

    uint2 oh = *reinterpret_cast<const uint2*>(rawO + e);
    uint2 fh = *reinterpret_cast<const uint2*>(rawF + e);
    const __half2* op = reinterpret_cast<const __half2*>(&oh);
    const __half2* fp = reinterpret_cast<const __half2*>(&fh);
    float2 o01 = __half22float2(op[0]), o23 = __half22float2(op[1]);
    float2 f01 = __half22float2(fp[0]), f23 = __half22float2(fp[1]);

    float4 ft = *reinterpret_cast<const float4*>(feats + e);
    float4 mk = *reinterpret_cast<const float4*>(mask + (size_t)b * NVC + col);

    float4 r;
    r.x = ft.x + (mk.x > 0.0f ? fmaxf(fmaf(o01.x, ao, co), 0.0f) + fmaxf(fmaf(f01.x, af, cf), 0.0f) : 0.0f);
    r.y = ft.y + (mk.y > 0.0f ? fmaxf(fmaf(o01.y, ao, co), 0.0f) + fmaxf(fmaf(f01.y, af, cf), 0.0f) : 0.0f);
    r.z = ft.z + (mk.z > 0.0f ? fmaxf(fmaf(o23.x, ao, co), 0.0f) + fmaxf(fmaf(f23.x, af, cf), 0.0f) : 0.0f);
    r.w = ft.w + (mk.w > 0.0f ? fmaxf(fmaf(o23.y, ao, co), 0.0f) + fmaxf(fmaf(f23.y, af, cf), 0.0f) : 0.0f);
    *reinterpret_cast<float4*>(out + e) = r;
}

extern "C" void kernel_launch(void* const* d_in, const int* in_sizes, int n_in,
                              void* d_out, int out_size)
{
    const float* feats = (const float*)d_in[0];
    const float* mask  = (const float*)d_in[1];
    const float* We    = (const float*)d_in[2];
    const float* be    = (const float*)d_in[3];
    const float* ge    = (const float*)d_in[4];
    const float* bne   = (const float*)d_in[5];
    const float* Wa    = (const float*)d_in[6];
    const float* ba    = (const float*)d_in[7];
    const float* ga    = (const float*)d_in[8];
    const float* bna   = (const float*)d_in[9];
    const float* Wo    = (const float*)d_in[10];
    const float* bo    = (const float*)d_in[11];
    const float* go    = (const float*)d_in[12];
    const float* bno   = (const float*)d_in[13];
    const float* Wf    = (const float*)d_in[14];
    const float* bf    = (const float*)d_in[15];
    const float* gf    = (const float*)d_in[16];
    const float* bnf   = (const float*)d_in[17];
    float* out = (float*)d_out;

    float *st;
    __half *emb, *bufa, *bufb, *whi;
    cudaGetSymbolAddress((void**)&emb,  g_emb);
    cudaGetSymbolAddress((void**)&bufa, g_bufa);
    cudaGetSymbolAddress((void**)&bufb, g_bufb);
    cudaGetSymbolAddress((void**)&st,   g_stats);
    cudaGetSymbolAddress((void**)&whi,  g_whi);

    constexpr int SM1 = SmemCfg<64, 256, 4>::TOTAL;
    constexpr int SM2 = SmemCfg<128, 64, 2>::TOTAL;
    constexpr int SM3 = SmemCfg<128, 256, 2>::TOTAL;
    cudaFuncSetAttribute(mma_layer<64, 256, 64, 0, false>,
                         cudaFuncAttributeMaxDynamicSharedMemorySize, SM1);
    cudaFuncSetAttribute(mma_layer<256, 64, 128, 1, true>,
                         cudaFuncAttributeMaxDynamicSharedMemorySize, SM2);
    cudaFuncSetAttribute(mma_layer<256, 256, 128, 1, true>,
                         cudaFuncAttributeMaxDynamicSharedMemorySize, SM3);
    cudaFuncSetAttribute(mma_layer<256, 256, 128, 2, true>,
                         cudaFuncAttributeMaxDynamicSharedMemorySize, SM3);

    zero_stats<<<8, 256>>>();
    split_weights<<<640, 256>>>(We, Wa, Wo, Wf);

    // L1 (e): rawE(fp16) = We @ feats(fp32) + be, masked
    mma_layer<64, 256, 64, 0, false><<<PGRID, 256, SM1>>>(
        feats, whi + WOFF_E, be, mask,
        nullptr, nullptr, nullptr, nullptr, nullptr,
        emb, st + 0, st + 64);

    // L2 (v-slice of a): X = bn_e(rawE); rawV(fp16) = Wa_v @ X + ba_v, masked
    mma_layer<256, 64, 128, 1, true><<<PGRID, 256, SM2>>>(
        emb, whi + WOFF_A, ba + 512, mask,
        st + 0, st + 64, ge, bne, nullptr,
        bufa, st + 128, st + 384);

    // L3 (o): X = bn_v(rawV); rawO(fp16) = Wo @ X + bo, masked
    mma_layer<256, 256, 128, 1, true><<<PGRID, 256, SM3>>>(
        bufa, whi + WOFF_O, bo, mask,
        st + 128, st + 384, ga + 512, bna + 512, nullptr,
        bufb, st + 640, st + 896);

    // L4 (f): X = feats + bn_o(rawO); rawF(fp16) = Wf @ X + bf, masked
    mma_layer<256, 256, 128, 2, true><<<PGRID, 256, SM3>>>(
        bufb, whi + WOFF_F, bf, mask,
        st + 640, st + 896, go, bno, feats,
        bufa, st + 1152, st + 1408);

    // out = feats + bn_o(rawO) + bn_f(rawF)
    final_fuse<<<(NB * 256 * NVC / 4 + 255) / 256, 256>>>(
        bufb, bufa, feats, mask, st, go, bno, gf, bnf, out);
}